// round 11
// baseline (speedup 1.0000x reference)
#include <cuda_runtime.h>
#include <cstdint>

// NerfRender integrate v8: v7 conflict-free c layout, shrunk to 24 owners
// (672 u32), cheap cp.async addressing, finite pad. One warp per ray.
// R = 65536, N = 192 (t has 193). Output: rgb [R,3] then wi [R,192].

#define NP1 193
#define NS  192
#define VR  8
#define WPB 8
#define SH_C 256              // u32 offset of c region
#define SH_PER_WARP 928       // 256 (t) + 672 (c: 24 lanes * 28 floats)
#define FULL 0xffffffffu
#define PAD_BITS 0x7149f2cau  // 1e30f: sorts above all real t, finite math

typedef uint32_t u32;

__device__ __forceinline__ void cp_async16(u32 saddr, const void* gptr) {
    asm volatile("cp.async.cg.shared.global [%0], [%1], 16;\n" :: "r"(saddr), "l"(gptr));
}
__device__ __forceinline__ void cp_async_commit() {
    asm volatile("cp.async.commit_group;\n" ::: "memory");
}
__device__ __forceinline__ void cp_async_wait_all() {
    asm volatile("cp.async.wait_group 0;\n" ::: "memory");
}

// forced IMAD (fma pipe): d = a*b + c (mod 2^32)
__device__ __forceinline__ u32 madlo(u32 a, u32 b, u32 c) {
    u32 d; asm("mad.lo.u32 %0, %1, %2, %3;" : "=r"(d) : "r"(a), "r"(b), "r"(c));
    return d;
}

// ---- lane bits ---------------------------------------------------------------
struct LB { bool b0, b1, b2, b3, b4; };
template <int I>
__device__ __forceinline__ bool getb(const LB& lb) {
    if constexpr (I == 0)      return lb.b0;
    else if constexpr (I == 1) return lb.b1;
    else if constexpr (I == 2) return lb.b2;
    else if constexpr (I == 3) return lb.b3;
    else                       return lb.b4;
}

// ---- comparator, min to a, exact max recovery on FMA pipe ----------------------
__device__ __forceinline__ void ce(u32& a, u32& b, u32 one, u32 m1) {
    u32 mn = min(a, b);             // IMNMX.U32 (ALU)
    u32 s  = madlo(a, one, b);      // IMAD (FMA): a + b
    b = madlo(mn, m1, s);           // IMAD (FMA): s - mn == max, exact
    a = mn;
}

#define CE(x, y) ce(v[x], v[y], one, m1)
__device__ __forceinline__ void stage_J1(u32 (&v)[VR], u32 one, u32 m1) {
    CE(0,1); CE(2,3); CE(4,5); CE(6,7);
}
__device__ __forceinline__ void stage_J2(u32 (&v)[VR], u32 one, u32 m1) {
    CE(0,2); CE(1,3); CE(4,6); CE(5,7);
}
__device__ __forceinline__ void stage_J4(u32 (&v)[VR], u32 one, u32 m1) {
    CE(0,4); CE(1,5); CE(2,6); CE(3,7);
}
__device__ __forceinline__ void stage_rev4(u32 (&v)[VR], u32 one, u32 m1) {
    CE(0,3); CE(1,2); CE(4,7); CE(5,6);
}
__device__ __forceinline__ void stage_rev8(u32 (&v)[VR], u32 one, u32 m1) {
    CE(0,7); CE(1,6); CE(2,5); CE(3,4);
}
#undef CE

// cross-lane reversal: partner lane^LMASK, partner reg 7-r; keepMin = !laneBit(KB)
template <int LMASK, int KB>
__device__ __forceinline__ void rev_cross(u32 (&v)[VR], const LB& lb) {
    u32 o[VR];
#pragma unroll
    for (int r = 0; r < VR; r++) o[r] = __shfl_xor_sync(FULL, v[7 - r], LMASK);
    const bool keep = !getb<KB>(lb);
#pragma unroll
    for (int r = 0; r < VR; r++)
        v[r] = keep ? min(v[r], o[r]) : max(v[r], o[r]);   // 1 IMNMX(P)
}
// cross-lane halving: partner lane^LJ, same reg
template <int LJ, int KB>
__device__ __forceinline__ void halv_cross(u32 (&v)[VR], const LB& lb) {
    u32 o[VR];
#pragma unroll
    for (int r = 0; r < VR; r++) o[r] = __shfl_xor_sync(FULL, v[r], LJ);
    const bool keep = !getb<KB>(lb);
#pragma unroll
    for (int r = 0; r < VR; r++)
        v[r] = keep ? min(v[r], o[r]) : max(v[r], o[r]);
}

__global__ __launch_bounds__(WPB * 32)
void nerf_integrate_kernel(const float* __restrict__ t,
                           const float* __restrict__ sigma,
                           const float* __restrict__ c,
                           float* __restrict__ out_rgb,
                           float* __restrict__ out_wi,
                           int R) {
    const int warp = threadIdx.x >> 5;
    const int lane = threadIdx.x & 31;
    const int ray  = blockIdx.x * WPB + warp;
    if (ray >= R) return;

    __shared__ u32 sh[WPB][SH_PER_WARP];
    u32* shw = sh[warp];

    const LB lb = { (lane & 1) != 0, (lane & 2) != 0, (lane & 4) != 0,
                    (lane & 8) != 0, (lane & 16) != 0 };

    // opaque constants so ptxas keeps mad.lo as IMAD on the fma pipe
    const u32 one = __shfl_sync(FULL, 1u, 0);
    const u32 m1  = 0u - one;

    const u32*   trow = reinterpret_cast<const u32*>(t) + (size_t)ray * NP1;
    const float* srow = sigma + (size_t)ray * NS;
    const float* crow = c + (size_t)ray * NS * 3;

    // ---- 1. t loads (bit patterns), coalesced ---------------------------
    u32 tv[6];
#pragma unroll
    for (int r = 0; r < 6; r++) tv[r] = __ldg(trow + r * 32 + lane);
    const u32 t192 = (lane == 0) ? __ldg(trow + 192) : PAD_BITS;

    // ---- 2. prefetch c via cp.async into padded layout --------------------
    // chunk g (0..143): owner=g/6, slot=g%6 -> byte dst = owner*112 + slot*16
    //                   = 16*(g + g/6)
    {
        const u32 shc = (u32)__cvta_generic_to_shared(shw + SH_C);
        const float4* c4 = reinterpret_cast<const float4*>(crow);
#pragma unroll
        for (int e = 0; e < 5; e++) {
            const u32 g = e * 32 + lane;
            if (e < 4 || lane < 16) {
                cp_async16(shc + 16u * (g + g / 6u), c4 + g);
            }
        }
        cp_async_commit();
    }

    // ---- 3. stage t, reload blocked -----------------------------------------
#pragma unroll
    for (int r = 0; r < 6; r++) shw[r * 32 + lane] = tv[r];
    shw[192 + lane] = t192;
    shw[224 + lane] = PAD_BITS;
    __syncwarp();

    u32 v[VR];
    {
        const uint4* p = reinterpret_cast<const uint4*>(shw + lane * VR);
        uint4 a = p[0], b = p[1];
        v[0]=a.x; v[1]=a.y; v[2]=a.z; v[3]=a.w;
        v[4]=b.x; v[5]=b.y; v[6]=b.z; v[7]=b.w;
    }

    // ---- 4. reversal-form bitonic sort (uint domain) ------------------------
    stage_J1(v, one, m1);                                            // m=2
    stage_rev4(v, one, m1); stage_J1(v, one, m1);                    // m=4
    stage_rev8(v, one, m1); stage_J2(v, one, m1); stage_J1(v, one, m1); // m=8
    rev_cross<1, 0>(v, lb);                                          // m=16
    stage_J4(v, one, m1); stage_J2(v, one, m1); stage_J1(v, one, m1);
    rev_cross<3, 1>(v, lb);                                          // m=32
    halv_cross<1, 0>(v, lb);
    stage_J4(v, one, m1); stage_J2(v, one, m1); stage_J1(v, one, m1);
    rev_cross<7, 2>(v, lb);                                          // m=64
    halv_cross<2, 1>(v, lb); halv_cross<1, 0>(v, lb);
    stage_J4(v, one, m1); stage_J2(v, one, m1); stage_J1(v, one, m1);
    rev_cross<15, 3>(v, lb);                                         // m=128
    halv_cross<4, 2>(v, lb); halv_cross<2, 1>(v, lb); halv_cross<1, 0>(v, lb);
    stage_J4(v, one, m1); stage_J2(v, one, m1); stage_J1(v, one, m1);
    rev_cross<31, 4>(v, lb);                                         // m=256
    halv_cross<8, 3>(v, lb); halv_cross<4, 2>(v, lb);
    halv_cross<2, 1>(v, lb); halv_cross<1, 0>(v, lb);
    stage_J4(v, one, m1); stage_J2(v, one, m1); stage_J1(v, one, m1);

    // ---- 5. back to float, boundary, sigma, sdt prefix -----------------------
    float f[VR];
#pragma unroll
    for (int e = 0; e < VR; e++) f[e] = __uint_as_float(v[e]);

    const float tnext = __uint_as_float(__shfl_down_sync(FULL, v[0], 1));
    const bool active = (lane < 24);

    float pfx[VR];
    {
        float4 s0 = make_float4(0.f,0.f,0.f,0.f), s1 = s0;
        if (active) {
            const float4* sp = reinterpret_cast<const float4*>(srow + lane * VR);
            s0 = __ldg(sp); s1 = __ldg(sp + 1);
        }
        const float sarr[VR] = {s0.x,s0.y,s0.z,s0.w,s1.x,s1.y,s1.z,s1.w};
        float run = 0.f;
#pragma unroll
        for (int e = 0; e < VR; e++) {
            float tn = (e < VR - 1) ? f[e + 1] : tnext;
            run += sarr[e] * (tn - f[e]);   // inactive lanes: 0 * finite = 0
            pfx[e] = run;
        }
    }

    // ---- 6. warp exclusive scan ------------------------------------------------
    const float tot = pfx[VR - 1];
    float inc = tot;
#pragma unroll
    for (int d = 1; d < 32; d <<= 1) {
        float y = __shfl_up_sync(FULL, inc, d);
        if (lane >= d) inc += y;
    }
    const float excl = inc - tot;

    // ---- 7. weights ---------------------------------------------------------------
    float w[VR];
    {
        float prevE = __expf(-excl);
#pragma unroll
        for (int e = 0; e < VR; e++) {
            float E = __expf(-(excl + pfx[e]));
            w[e] = prevE - E;
            prevE = E;
        }
    }

    // ---- 8. wi out: direct STG.128 (blocked) ----------------------------------------
    if (active) {
        float4* wp = reinterpret_cast<float4*>(out_wi + (size_t)ray * NS + lane * VR);
        wp[0] = make_float4(w[0], w[1], w[2], w[3]);
        wp[1] = make_float4(w[4], w[5], w[6], w[7]);
    }

    // ---- 9. rgb from padded shared c (conflict-free), compile-time channels ----------
    cp_async_wait_all();
    __syncwarp();

    float a0 = 0.f, a1 = 0.f, a2 = 0.f;
    if (active) {
        const float* cl = reinterpret_cast<const float*>(shw + SH_C) + lane * 28;
#pragma unroll
        for (int q = 0; q < 6; q++) {
            float4 cv = *reinterpret_cast<const float4*>(cl + 4 * q);
            const float cj[4] = {cv.x, cv.y, cv.z, cv.w};
#pragma unroll
            for (int j = 0; j < 4; j++) {
                const int k  = 4 * q + j;
                const int e  = k / 3;
                const int ch = k - 3 * e;
                const float p = w[e] * cj[j];
                if (ch == 0)      a0 += p;
                else if (ch == 1) a1 += p;
                else              a2 += p;
            }
        }
    }

    // ---- 10. reduce rgb, write ---------------------------------------------------------
#pragma unroll
    for (int d = 16; d > 0; d >>= 1) {
        a0 += __shfl_xor_sync(FULL, a0, d);
        a1 += __shfl_xor_sync(FULL, a1, d);
        a2 += __shfl_xor_sync(FULL, a2, d);
    }
    if (lane < 3) {
        const float val = (lane == 0) ? a0 : ((lane == 1) ? a1 : a2);
        out_rgb[(size_t)ray * 3 + lane] = val;
    }
}

extern "C" void kernel_launch(void* const* d_in, const int* in_sizes, int n_in,
                              void* d_out, int out_size) {
    const float* t     = (const float*)d_in[0];
    const float* sigma = (const float*)d_in[1];
    const float* c     = (const float*)d_in[2];

    const int R = in_sizes[0] / NP1;

    float* out_rgb = (float*)d_out;
    float* out_wi  = out_rgb + (size_t)R * 3;

    const int blocks = (R + WPB - 1) / WPB;
    nerf_integrate_kernel<<<blocks, WPB * 32>>>(t, sigma, c, out_rgb, out_wi, R);
}

// round 12
// speedup vs baseline: 1.0343x; 1.0343x over previous
#include <cuda_runtime.h>
#include <cstdint>

// NerfRender integrate v9: v6 footprint + XOR-swizzled t staging (conflict-free
// LDS.128) + chunk-padded c region (+80B/warp). One warp per ray.
// R = 65536, N = 192 (t has 193). Output: rgb [R,3] then wi [R,192].

#define NP1 193
#define NS  192
#define VR  8
#define WPB 8
#define SH_C 256              // u32 offset of c region
#define SH_PER_WARP 852       // 256 (t) + 596 (c: 149 chunks of 16B)
#define FULL 0xffffffffu
#define PAD_BITS 0x7149f2cau  // 1e30f: sorts above all real t, finite math

typedef uint32_t u32;

__device__ __forceinline__ void cp_async16(u32 saddr, const void* gptr) {
    asm volatile("cp.async.cg.shared.global [%0], [%1], 16;\n" :: "r"(saddr), "l"(gptr));
}
__device__ __forceinline__ void cp_async_commit() {
    asm volatile("cp.async.commit_group;\n" ::: "memory");
}
__device__ __forceinline__ void cp_async_wait_all() {
    asm volatile("cp.async.wait_group 0;\n" ::: "memory");
}

// forced IMAD (fma pipe): d = a*b + c (mod 2^32)
__device__ __forceinline__ u32 madlo(u32 a, u32 b, u32 c) {
    u32 d; asm("mad.lo.u32 %0, %1, %2, %3;" : "=r"(d) : "r"(a), "r"(b), "r"(c));
    return d;
}

// ---- lane bits ---------------------------------------------------------------
struct LB { bool b0, b1, b2, b3, b4; };
template <int I>
__device__ __forceinline__ bool getb(const LB& lb) {
    if constexpr (I == 0)      return lb.b0;
    else if constexpr (I == 1) return lb.b1;
    else if constexpr (I == 2) return lb.b2;
    else if constexpr (I == 3) return lb.b3;
    else                       return lb.b4;
}

// ---- comparator, min to a, exact max recovery on FMA pipe ----------------------
__device__ __forceinline__ void ce(u32& a, u32& b, u32 one, u32 m1) {
    u32 mn = min(a, b);             // IMNMX.U32 (ALU)
    u32 s  = madlo(a, one, b);      // IMAD (FMA): a + b
    b = madlo(mn, m1, s);           // IMAD (FMA): s - mn == max, exact
    a = mn;
}

#define CE(x, y) ce(v[x], v[y], one, m1)
__device__ __forceinline__ void stage_J1(u32 (&v)[VR], u32 one, u32 m1) {
    CE(0,1); CE(2,3); CE(4,5); CE(6,7);
}
__device__ __forceinline__ void stage_J2(u32 (&v)[VR], u32 one, u32 m1) {
    CE(0,2); CE(1,3); CE(4,6); CE(5,7);
}
__device__ __forceinline__ void stage_J4(u32 (&v)[VR], u32 one, u32 m1) {
    CE(0,4); CE(1,5); CE(2,6); CE(3,7);
}
__device__ __forceinline__ void stage_rev4(u32 (&v)[VR], u32 one, u32 m1) {
    CE(0,3); CE(1,2); CE(4,7); CE(5,6);
}
__device__ __forceinline__ void stage_rev8(u32 (&v)[VR], u32 one, u32 m1) {
    CE(0,7); CE(1,6); CE(2,5); CE(3,4);
}
#undef CE

// cross-lane reversal: partner lane^LMASK, partner reg 7-r; keepMin = !laneBit(KB)
template <int LMASK, int KB>
__device__ __forceinline__ void rev_cross(u32 (&v)[VR], const LB& lb) {
    u32 o[VR];
#pragma unroll
    for (int r = 0; r < VR; r++) o[r] = __shfl_xor_sync(FULL, v[7 - r], LMASK);
    const bool keep = !getb<KB>(lb);
#pragma unroll
    for (int r = 0; r < VR; r++)
        v[r] = keep ? min(v[r], o[r]) : max(v[r], o[r]);   // 1 IMNMX(P)
}
// cross-lane halving: partner lane^LJ, same reg
template <int LJ, int KB>
__device__ __forceinline__ void halv_cross(u32 (&v)[VR], const LB& lb) {
    u32 o[VR];
#pragma unroll
    for (int r = 0; r < VR; r++) o[r] = __shfl_xor_sync(FULL, v[r], LJ);
    const bool keep = !getb<KB>(lb);
#pragma unroll
    for (int r = 0; r < VR; r++)
        v[r] = keep ? min(v[r], o[r]) : max(v[r], o[r]);
}

__global__ __launch_bounds__(WPB * 32)
void nerf_integrate_kernel(const float* __restrict__ t,
                           const float* __restrict__ sigma,
                           const float* __restrict__ c,
                           float* __restrict__ out_rgb,
                           float* __restrict__ out_wi,
                           int R) {
    const int warp = threadIdx.x >> 5;
    const int lane = threadIdx.x & 31;
    const int ray  = blockIdx.x * WPB + warp;
    if (ray >= R) return;

    __shared__ u32 sh[WPB][SH_PER_WARP];
    u32* shw = sh[warp];

    const LB lb = { (lane & 1) != 0, (lane & 2) != 0, (lane & 4) != 0,
                    (lane & 8) != 0, (lane & 16) != 0 };

    // opaque constants so ptxas keeps mad.lo as IMAD on the fma pipe
    const u32 one = __shfl_sync(FULL, 1u, 0);
    const u32 m1  = 0u - one;

    const u32*   trow = reinterpret_cast<const u32*>(t) + (size_t)ray * NP1;
    const float* srow = sigma + (size_t)ray * NS;
    const float* crow = c + (size_t)ray * NS * 3;

    // ---- 1. t loads (bit patterns), coalesced ---------------------------
    u32 tv[6];
#pragma unroll
    for (int r = 0; r < 6; r++) tv[r] = __ldg(trow + r * 32 + lane);
    const u32 t192 = (lane == 0) ? __ldg(trow + 192) : PAD_BITS;

    // ---- 2. prefetch c via cp.async, chunk-padded: phys = g + g/24 --------
    {
        const u32 shc = (u32)__cvta_generic_to_shared(shw + SH_C);
        const float4* c4 = reinterpret_cast<const float4*>(crow);
#pragma unroll
        for (int e = 0; e < 5; e++) {
            const u32 g = e * 32 + lane;
            if (e < 4 || lane < 16) {
                cp_async16(shc + 16u * (g + g / 24u), c4 + g);
            }
        }
        cp_async_commit();
    }

    // ---- 3. stage t XOR-swizzled, reload blocked conflict-free -----------
    // store: word L = 32r+lane -> phys = L ^ ((r&7)<<2)  (lane permutation)
#pragma unroll
    for (int r = 0; r < 6; r++)
        shw[32 * r + (lane ^ ((r & 7) << 2))] = tv[r];
    shw[192 + (lane ^ 24)] = t192;          // r = 6
    shw[224 + (lane ^ 28)] = PAD_BITS;      // r = 7
    __syncwarp();

    u32 v[VR];
    {
        const u32 sw = ((u32)(lane >> 2) & 7u) << 2;
        const u32 p0 = ((u32)(8 * lane)) ^ sw;
        const u32 p1 = ((u32)(8 * lane + 4)) ^ sw;
        uint4 a = *reinterpret_cast<const uint4*>(shw + p0);
        uint4 b = *reinterpret_cast<const uint4*>(shw + p1);
        v[0]=a.x; v[1]=a.y; v[2]=a.z; v[3]=a.w;
        v[4]=b.x; v[5]=b.y; v[6]=b.z; v[7]=b.w;
    }

    // ---- 4. reversal-form bitonic sort (uint domain) ------------------------
    stage_J1(v, one, m1);                                            // m=2
    stage_rev4(v, one, m1); stage_J1(v, one, m1);                    // m=4
    stage_rev8(v, one, m1); stage_J2(v, one, m1); stage_J1(v, one, m1); // m=8
    rev_cross<1, 0>(v, lb);                                          // m=16
    stage_J4(v, one, m1); stage_J2(v, one, m1); stage_J1(v, one, m1);
    rev_cross<3, 1>(v, lb);                                          // m=32
    halv_cross<1, 0>(v, lb);
    stage_J4(v, one, m1); stage_J2(v, one, m1); stage_J1(v, one, m1);
    rev_cross<7, 2>(v, lb);                                          // m=64
    halv_cross<2, 1>(v, lb); halv_cross<1, 0>(v, lb);
    stage_J4(v, one, m1); stage_J2(v, one, m1); stage_J1(v, one, m1);
    rev_cross<15, 3>(v, lb);                                         // m=128
    halv_cross<4, 2>(v, lb); halv_cross<2, 1>(v, lb); halv_cross<1, 0>(v, lb);
    stage_J4(v, one, m1); stage_J2(v, one, m1); stage_J1(v, one, m1);
    rev_cross<31, 4>(v, lb);                                         // m=256
    halv_cross<8, 3>(v, lb); halv_cross<4, 2>(v, lb);
    halv_cross<2, 1>(v, lb); halv_cross<1, 0>(v, lb);
    stage_J4(v, one, m1); stage_J2(v, one, m1); stage_J1(v, one, m1);

    // ---- 5. back to float, boundary, sigma, sdt prefix -----------------------
    float f[VR];
#pragma unroll
    for (int e = 0; e < VR; e++) f[e] = __uint_as_float(v[e]);

    const float tnext = __uint_as_float(__shfl_down_sync(FULL, v[0], 1));
    const bool active = (lane < 24);

    float pfx[VR];
    {
        float4 s0 = make_float4(0.f,0.f,0.f,0.f), s1 = s0;
        if (active) {
            const float4* sp = reinterpret_cast<const float4*>(srow + lane * VR);
            s0 = __ldg(sp); s1 = __ldg(sp + 1);
        }
        const float sarr[VR] = {s0.x,s0.y,s0.z,s0.w,s1.x,s1.y,s1.z,s1.w};
        float run = 0.f;
#pragma unroll
        for (int e = 0; e < VR; e++) {
            float tn = (e < VR - 1) ? f[e + 1] : tnext;
            run += sarr[e] * (tn - f[e]);   // inactive lanes: 0 * finite = 0
            pfx[e] = run;
        }
    }

    // ---- 6. warp exclusive scan ------------------------------------------------
    const float tot = pfx[VR - 1];
    float inc = tot;
#pragma unroll
    for (int d = 1; d < 32; d <<= 1) {
        float y = __shfl_up_sync(FULL, inc, d);
        if (lane >= d) inc += y;
    }
    const float excl = inc - tot;

    // ---- 7. weights ---------------------------------------------------------------
    float w[VR];
    {
        float prevE = __expf(-excl);
#pragma unroll
        for (int e = 0; e < VR; e++) {
            float E = __expf(-(excl + pfx[e]));
            w[e] = prevE - E;
            prevE = E;
        }
    }

    // ---- 8. wi out: direct STG.128 (blocked) ----------------------------------------
    if (active) {
        float4* wp = reinterpret_cast<float4*>(out_wi + (size_t)ray * NS + lane * VR);
        wp[0] = make_float4(w[0], w[1], w[2], w[3]);
        wp[1] = make_float4(w[4], w[5], w[6], w[7]);
    }

    // ---- 9. rgb from padded shared c (conflict-free), compile-time channels ----------
    cp_async_wait_all();
    __syncwarp();

    float a0 = 0.f, a1 = 0.f, a2 = 0.f;
    if (active) {
        // lane's chunks: phys = 6*lane + (lane>>2); words = 4*phys
        const float* cl = reinterpret_cast<const float*>(shw + SH_C)
                        + 4 * (6 * lane + (lane >> 2));
#pragma unroll
        for (int q = 0; q < 6; q++) {
            float4 cv = *reinterpret_cast<const float4*>(cl + 4 * q);
            const float cj[4] = {cv.x, cv.y, cv.z, cv.w};
#pragma unroll
            for (int j = 0; j < 4; j++) {
                const int k  = 4 * q + j;
                const int e  = k / 3;
                const int ch = k - 3 * e;
                const float p = w[e] * cj[j];
                if (ch == 0)      a0 += p;
                else if (ch == 1) a1 += p;
                else              a2 += p;
            }
        }
    }

    // ---- 10. reduce rgb, write ---------------------------------------------------------
#pragma unroll
    for (int d = 16; d > 0; d >>= 1) {
        a0 += __shfl_xor_sync(FULL, a0, d);
        a1 += __shfl_xor_sync(FULL, a1, d);
        a2 += __shfl_xor_sync(FULL, a2, d);
    }
    if (lane < 3) {
        const float val = (lane == 0) ? a0 : ((lane == 1) ? a1 : a2);
        out_rgb[(size_t)ray * 3 + lane] = val;
    }
}

extern "C" void kernel_launch(void* const* d_in, const int* in_sizes, int n_in,
                              void* d_out, int out_size) {
    const float* t     = (const float*)d_in[0];
    const float* sigma = (const float*)d_in[1];
    const float* c     = (const float*)d_in[2];

    const int R = in_sizes[0] / NP1;

    float* out_rgb = (float*)d_out;
    float* out_wi  = out_rgb + (size_t)R * 3;

    const int blocks = (R + WPB - 1) / WPB;
    nerf_integrate_kernel<<<blocks, WPB * 32>>>(t, sigma, c, out_rgb, out_wi, R);
}

// round 13
// speedup vs baseline: 1.0779x; 1.0421x over previous
#include <cuda_runtime.h>
#include <cstdint>

// NerfRender integrate v10: v6 layout (lean addressing) + finite pad (no
// guards) + Batcher-19 in-register sort front. One warp per ray.
// R = 65536, N = 192 (t has 193). Output: rgb [R,3] then wi [R,192].

#define NP1 193
#define NS  192
#define VR  8
#define WPB 8
#define SH_C 256
#define SH_PER_WARP 832       // 256 (t) + 576 (c contiguous)
#define FULL 0xffffffffu
#define PAD_BITS 0x7149f2cau  // 1e30f: sorts above all real t, finite math

typedef uint32_t u32;

__device__ __forceinline__ void cp_async16(u32 saddr, const void* gptr) {
    asm volatile("cp.async.cg.shared.global [%0], [%1], 16;\n" :: "r"(saddr), "l"(gptr));
}
__device__ __forceinline__ void cp_async_commit() {
    asm volatile("cp.async.commit_group;\n" ::: "memory");
}
__device__ __forceinline__ void cp_async_wait_all() {
    asm volatile("cp.async.wait_group 0;\n" ::: "memory");
}

// forced IMAD: d = a*b + c (mod 2^32)
__device__ __forceinline__ u32 madlo(u32 a, u32 b, u32 c) {
    u32 d; asm("mad.lo.u32 %0, %1, %2, %3;" : "=r"(d) : "r"(a), "r"(b), "r"(c));
    return d;
}

// ---- lane bits ---------------------------------------------------------------
struct LB { bool b0, b1, b2, b3, b4; };
template <int I>
__device__ __forceinline__ bool getb(const LB& lb) {
    if constexpr (I == 0)      return lb.b0;
    else if constexpr (I == 1) return lb.b1;
    else if constexpr (I == 2) return lb.b2;
    else if constexpr (I == 3) return lb.b3;
    else                       return lb.b4;
}

// ---- comparator, min to a, exact max recovery via IMAD -------------------------
__device__ __forceinline__ void ce(u32& a, u32& b, u32 one, u32 m1) {
    u32 mn = min(a, b);             // IMNMX.U32
    u32 s  = madlo(a, one, b);      // a + b
    b = madlo(mn, m1, s);           // s - mn == max, exact
    a = mn;
}

// Batcher odd-even sort-8 (19 comparators), ascending
#define CE(x, y) ce(v[x], v[y], one, m1)
__device__ __forceinline__ void batcher8(u32 (&v)[VR], u32 one, u32 m1) {
    CE(0,1); CE(2,3); CE(4,5); CE(6,7);
    CE(0,2); CE(1,3); CE(4,6); CE(5,7);
    CE(1,2); CE(5,6);
    CE(0,4); CE(1,5); CE(2,6); CE(3,7);
    CE(2,4); CE(3,5);
    CE(1,2); CE(3,4); CE(5,6);
}
__device__ __forceinline__ void stage_J1(u32 (&v)[VR], u32 one, u32 m1) {
    CE(0,1); CE(2,3); CE(4,5); CE(6,7);
}
__device__ __forceinline__ void stage_J2(u32 (&v)[VR], u32 one, u32 m1) {
    CE(0,2); CE(1,3); CE(4,6); CE(5,7);
}
__device__ __forceinline__ void stage_J4(u32 (&v)[VR], u32 one, u32 m1) {
    CE(0,4); CE(1,5); CE(2,6); CE(3,7);
}
#undef CE

// cross-lane reversal: partner lane^LMASK, partner reg 7-r; keepMin = !laneBit(KB)
template <int LMASK, int KB>
__device__ __forceinline__ void rev_cross(u32 (&v)[VR], const LB& lb) {
    u32 o[VR];
#pragma unroll
    for (int r = 0; r < VR; r++) o[r] = __shfl_xor_sync(FULL, v[7 - r], LMASK);
    const bool keep = !getb<KB>(lb);
#pragma unroll
    for (int r = 0; r < VR; r++)
        v[r] = keep ? min(v[r], o[r]) : max(v[r], o[r]);   // 1 IMNMX(P)
}
// cross-lane halving: partner lane^LJ, same reg
template <int LJ, int KB>
__device__ __forceinline__ void halv_cross(u32 (&v)[VR], const LB& lb) {
    u32 o[VR];
#pragma unroll
    for (int r = 0; r < VR; r++) o[r] = __shfl_xor_sync(FULL, v[r], LJ);
    const bool keep = !getb<KB>(lb);
#pragma unroll
    for (int r = 0; r < VR; r++)
        v[r] = keep ? min(v[r], o[r]) : max(v[r], o[r]);
}

__global__ __launch_bounds__(WPB * 32)
void nerf_integrate_kernel(const float* __restrict__ t,
                           const float* __restrict__ sigma,
                           const float* __restrict__ c,
                           float* __restrict__ out_rgb,
                           float* __restrict__ out_wi,
                           int R) {
    const int warp = threadIdx.x >> 5;
    const int lane = threadIdx.x & 31;
    const int ray  = blockIdx.x * WPB + warp;
    if (ray >= R) return;

    __shared__ u32 sh[WPB][SH_PER_WARP];
    u32* shw = sh[warp];

    const LB lb = { (lane & 1) != 0, (lane & 2) != 0, (lane & 4) != 0,
                    (lane & 8) != 0, (lane & 16) != 0 };

    // opaque constants so ptxas keeps mad.lo as IMAD
    const u32 one = __shfl_sync(FULL, 1u, 0);
    const u32 m1  = 0u - one;

    const u32*   trow = reinterpret_cast<const u32*>(t) + (size_t)ray * NP1;
    const float* srow = sigma + (size_t)ray * NS;
    const float* crow = c + (size_t)ray * NS * 3;

    // ---- 1. t loads (bit patterns), coalesced ---------------------------
    u32 tv[6];
#pragma unroll
    for (int r = 0; r < 6; r++) tv[r] = __ldg(trow + r * 32 + lane);
    const u32 t192 = (lane == 0) ? __ldg(trow + 192) : PAD_BITS;

    // ---- 2. prefetch c via cp.async (contiguous, zero addr math) ----------
    {
        const u32 shc = (u32)__cvta_generic_to_shared(shw + SH_C);
        const float4* c4 = reinterpret_cast<const float4*>(crow);
#pragma unroll
        for (int e = 0; e < 4; e++)
            cp_async16(shc + (e * 32 + lane) * 16, c4 + e * 32 + lane);
        if (lane < 16)
            cp_async16(shc + (128 + lane) * 16, c4 + 128 + lane);
        cp_async_commit();
    }

    // ---- 3. stage t, reload blocked -----------------------------------------
#pragma unroll
    for (int r = 0; r < 6; r++) shw[r * 32 + lane] = tv[r];
    shw[192 + lane] = t192;
    shw[224 + lane] = PAD_BITS;
    __syncwarp();

    u32 v[VR];
    {
        const uint4* p = reinterpret_cast<const uint4*>(shw + lane * VR);
        uint4 a = p[0], b = p[1];
        v[0]=a.x; v[1]=a.y; v[2]=a.z; v[3]=a.w;
        v[4]=b.x; v[5]=b.y; v[6]=b.z; v[7]=b.w;
    }

    // ---- 4. sort: Batcher-8 per lane, then reversal-form bitonic merges -----
    batcher8(v, one, m1);                                            // 8-sorted
    rev_cross<1, 0>(v, lb);                                          // m=16
    stage_J4(v, one, m1); stage_J2(v, one, m1); stage_J1(v, one, m1);
    rev_cross<3, 1>(v, lb);                                          // m=32
    halv_cross<1, 0>(v, lb);
    stage_J4(v, one, m1); stage_J2(v, one, m1); stage_J1(v, one, m1);
    rev_cross<7, 2>(v, lb);                                          // m=64
    halv_cross<2, 1>(v, lb); halv_cross<1, 0>(v, lb);
    stage_J4(v, one, m1); stage_J2(v, one, m1); stage_J1(v, one, m1);
    rev_cross<15, 3>(v, lb);                                         // m=128
    halv_cross<4, 2>(v, lb); halv_cross<2, 1>(v, lb); halv_cross<1, 0>(v, lb);
    stage_J4(v, one, m1); stage_J2(v, one, m1); stage_J1(v, one, m1);
    rev_cross<31, 4>(v, lb);                                         // m=256
    halv_cross<8, 3>(v, lb); halv_cross<4, 2>(v, lb);
    halv_cross<2, 1>(v, lb); halv_cross<1, 0>(v, lb);
    stage_J4(v, one, m1); stage_J2(v, one, m1); stage_J1(v, one, m1);

    // ---- 5. back to float, boundary, sigma, sdt prefix -----------------------
    float f[VR];
#pragma unroll
    for (int e = 0; e < VR; e++) f[e] = __uint_as_float(v[e]);

    const float tnext = __uint_as_float(__shfl_down_sync(FULL, v[0], 1));
    const bool active = (lane < 24);

    float pfx[VR];
    {
        float4 s0 = make_float4(0.f,0.f,0.f,0.f), s1 = s0;
        if (active) {
            const float4* sp = reinterpret_cast<const float4*>(srow + lane * VR);
            s0 = __ldg(sp); s1 = __ldg(sp + 1);
        }
        const float sarr[VR] = {s0.x,s0.y,s0.z,s0.w,s1.x,s1.y,s1.z,s1.w};
        float run = 0.f;
#pragma unroll
        for (int e = 0; e < VR; e++) {
            float tn = (e < VR - 1) ? f[e + 1] : tnext;
            run += sarr[e] * (tn - f[e]);   // pad lanes: 0 * finite = 0
            pfx[e] = run;
        }
    }

    // ---- 6. warp exclusive scan ------------------------------------------------
    const float tot = pfx[VR - 1];
    float inc = tot;
#pragma unroll
    for (int d = 1; d < 32; d <<= 1) {
        float y = __shfl_up_sync(FULL, inc, d);
        if (lane >= d) inc += y;
    }
    const float excl = inc - tot;

    // ---- 7. weights ---------------------------------------------------------------
    float w[VR];
    {
        float prevE = __expf(-excl);
#pragma unroll
        for (int e = 0; e < VR; e++) {
            float E = __expf(-(excl + pfx[e]));
            w[e] = prevE - E;
            prevE = E;
        }
    }

    // ---- 8. wi out: direct STG.128 (blocked) ----------------------------------------
    if (active) {
        float4* wp = reinterpret_cast<float4*>(out_wi + (size_t)ray * NS + lane * VR);
        wp[0] = make_float4(w[0], w[1], w[2], w[3]);
        wp[1] = make_float4(w[4], w[5], w[6], w[7]);
    }

    // ---- 9. rgb from shared c, compile-time channels ----------------------------------
    cp_async_wait_all();
    __syncwarp();

    float a0 = 0.f, a1 = 0.f, a2 = 0.f;
    if (active) {
        const float* cl = reinterpret_cast<const float*>(shw + SH_C) + lane * 24;
#pragma unroll
        for (int q = 0; q < 6; q++) {
            float4 cv = *reinterpret_cast<const float4*>(cl + 4 * q);
            const float cj[4] = {cv.x, cv.y, cv.z, cv.w};
#pragma unroll
            for (int j = 0; j < 4; j++) {
                const int k  = 4 * q + j;
                const int e  = k / 3;
                const int ch = k - 3 * e;
                const float p = w[e] * cj[j];
                if (ch == 0)      a0 += p;
                else if (ch == 1) a1 += p;
                else              a2 += p;
            }
        }
    }

    // ---- 10. reduce rgb, write ---------------------------------------------------------
#pragma unroll
    for (int d = 16; d > 0; d >>= 1) {
        a0 += __shfl_xor_sync(FULL, a0, d);
        a1 += __shfl_xor_sync(FULL, a1, d);
        a2 += __shfl_xor_sync(FULL, a2, d);
    }
    if (lane < 3) {
        const float val = (lane == 0) ? a0 : ((lane == 1) ? a1 : a2);
        out_rgb[(size_t)ray * 3 + lane] = val;
    }
}

extern "C" void kernel_launch(void* const* d_in, const int* in_sizes, int n_in,
                              void* d_out, int out_size) {
    const float* t     = (const float*)d_in[0];
    const float* sigma = (const float*)d_in[1];
    const float* c     = (const float*)d_in[2];

    const int R = in_sizes[0] / NP1;

    float* out_rgb = (float*)d_out;
    float* out_wi  = out_rgb + (size_t)R * 3;

    const int blocks = (R + WPB - 1) / WPB;
    nerf_integrate_kernel<<<blocks, WPB * 32>>>(t, sigma, c, out_rgb, out_wi, R);
}

// round 14
// speedup vs baseline: 1.1346x; 1.0526x over previous
#include <cuda_runtime.h>
#include <cstdint>

// NerfRender integrate v11: no t staging (sort network is placement-agnostic:
// strided loads feed register slots directly), c-only smem, Batcher-19 front,
// IMNMX+IMAD comparators, finite pad. One warp per ray.
// R = 65536, N = 192 (t has 193). Output: rgb [R,3] then wi [R,192].

#define NP1 193
#define NS  192
#define VR  8
#define WPB 8
#define SH_PER_WARP 576       // c only (144 chunks of 16B)
#define FULL 0xffffffffu
#define PAD_BITS 0x7149f2cau  // 1e30f: sorts above all real t, finite math

typedef uint32_t u32;

__device__ __forceinline__ void cp_async16(u32 saddr, const void* gptr) {
    asm volatile("cp.async.cg.shared.global [%0], [%1], 16;\n" :: "r"(saddr), "l"(gptr));
}
__device__ __forceinline__ void cp_async_commit() {
    asm volatile("cp.async.commit_group;\n" ::: "memory");
}
__device__ __forceinline__ void cp_async_wait_all() {
    asm volatile("cp.async.wait_group 0;\n" ::: "memory");
}

// forced IMAD: d = a*b + c (mod 2^32)
__device__ __forceinline__ u32 madlo(u32 a, u32 b, u32 c) {
    u32 d; asm("mad.lo.u32 %0, %1, %2, %3;" : "=r"(d) : "r"(a), "r"(b), "r"(c));
    return d;
}

// ---- lane bits ---------------------------------------------------------------
struct LB { bool b0, b1, b2, b3, b4; };
template <int I>
__device__ __forceinline__ bool getb(const LB& lb) {
    if constexpr (I == 0)      return lb.b0;
    else if constexpr (I == 1) return lb.b1;
    else if constexpr (I == 2) return lb.b2;
    else if constexpr (I == 3) return lb.b3;
    else                       return lb.b4;
}

// ---- comparator, min to a, exact max recovery via IMAD (FMA pipe) ---------------
__device__ __forceinline__ void ce(u32& a, u32& b, u32 one, u32 m1) {
    u32 mn = min(a, b);             // IMNMX.U32 (ALU)
    u32 s  = madlo(a, one, b);      // a + b
    b = madlo(mn, m1, s);           // s - mn == max, exact
    a = mn;
}

// Batcher odd-even sort-8 (19 comparators), ascending
#define CE(x, y) ce(v[x], v[y], one, m1)
__device__ __forceinline__ void batcher8(u32 (&v)[VR], u32 one, u32 m1) {
    CE(0,1); CE(2,3); CE(4,5); CE(6,7);
    CE(0,2); CE(1,3); CE(4,6); CE(5,7);
    CE(1,2); CE(5,6);
    CE(0,4); CE(1,5); CE(2,6); CE(3,7);
    CE(2,4); CE(3,5);
    CE(1,2); CE(3,4); CE(5,6);
}
__device__ __forceinline__ void stage_J1(u32 (&v)[VR], u32 one, u32 m1) {
    CE(0,1); CE(2,3); CE(4,5); CE(6,7);
}
__device__ __forceinline__ void stage_J2(u32 (&v)[VR], u32 one, u32 m1) {
    CE(0,2); CE(1,3); CE(4,6); CE(5,7);
}
__device__ __forceinline__ void stage_J4(u32 (&v)[VR], u32 one, u32 m1) {
    CE(0,4); CE(1,5); CE(2,6); CE(3,7);
}
#undef CE

// cross-lane reversal: partner lane^LMASK, partner reg 7-r; keepMin = !laneBit(KB)
template <int LMASK, int KB>
__device__ __forceinline__ void rev_cross(u32 (&v)[VR], const LB& lb) {
    u32 o[VR];
#pragma unroll
    for (int r = 0; r < VR; r++) o[r] = __shfl_xor_sync(FULL, v[7 - r], LMASK);
    const bool keep = !getb<KB>(lb);
#pragma unroll
    for (int r = 0; r < VR; r++)
        v[r] = keep ? min(v[r], o[r]) : max(v[r], o[r]);   // 1 IMNMX(P)
}
// cross-lane halving: partner lane^LJ, same reg
template <int LJ, int KB>
__device__ __forceinline__ void halv_cross(u32 (&v)[VR], const LB& lb) {
    u32 o[VR];
#pragma unroll
    for (int r = 0; r < VR; r++) o[r] = __shfl_xor_sync(FULL, v[r], LJ);
    const bool keep = !getb<KB>(lb);
#pragma unroll
    for (int r = 0; r < VR; r++)
        v[r] = keep ? min(v[r], o[r]) : max(v[r], o[r]);
}

__global__ __launch_bounds__(WPB * 32)
void nerf_integrate_kernel(const float* __restrict__ t,
                           const float* __restrict__ sigma,
                           const float* __restrict__ c,
                           float* __restrict__ out_rgb,
                           float* __restrict__ out_wi,
                           int R) {
    const int warp = threadIdx.x >> 5;
    const int lane = threadIdx.x & 31;
    const int ray  = blockIdx.x * WPB + warp;
    if (ray >= R) return;

    __shared__ u32 sh[WPB][SH_PER_WARP];    // c region only
    u32* shw = sh[warp];

    const LB lb = { (lane & 1) != 0, (lane & 2) != 0, (lane & 4) != 0,
                    (lane & 8) != 0, (lane & 16) != 0 };

    // opaque constants so ptxas keeps mad.lo as IMAD
    const u32 one = __shfl_sync(FULL, 1u, 0);
    const u32 m1  = 0u - one;

    const u32*   trow = reinterpret_cast<const u32*>(t) + (size_t)ray * NP1;
    const float* srow = sigma + (size_t)ray * NS;
    const float* crow = c + (size_t)ray * NS * 3;

    // ---- 1. t loads straight into sort slots (placement-agnostic network) --
    u32 v[VR];
#pragma unroll
    for (int r = 0; r < 6; r++) v[r] = __ldg(trow + r * 32 + lane);
    v[6] = (lane == 0) ? __ldg(trow + 192) : PAD_BITS;
    v[7] = PAD_BITS;

    // ---- 2. prefetch c via cp.async (contiguous) ----------------------------
    {
        const u32 shc = (u32)__cvta_generic_to_shared(shw);
        const float4* c4 = reinterpret_cast<const float4*>(crow);
#pragma unroll
        for (int e = 0; e < 4; e++)
            cp_async16(shc + (e * 32 + lane) * 16, c4 + e * 32 + lane);
        if (lane < 16)
            cp_async16(shc + (128 + lane) * 16, c4 + 128 + lane);
        cp_async_commit();
    }

    // ---- 3. sort: Batcher-8 per lane, then reversal-form bitonic merges -----
    batcher8(v, one, m1);                                            // 8-sorted
    rev_cross<1, 0>(v, lb);                                          // m=16
    stage_J4(v, one, m1); stage_J2(v, one, m1); stage_J1(v, one, m1);
    rev_cross<3, 1>(v, lb);                                          // m=32
    halv_cross<1, 0>(v, lb);
    stage_J4(v, one, m1); stage_J2(v, one, m1); stage_J1(v, one, m1);
    rev_cross<7, 2>(v, lb);                                          // m=64
    halv_cross<2, 1>(v, lb); halv_cross<1, 0>(v, lb);
    stage_J4(v, one, m1); stage_J2(v, one, m1); stage_J1(v, one, m1);
    rev_cross<15, 3>(v, lb);                                         // m=128
    halv_cross<4, 2>(v, lb); halv_cross<2, 1>(v, lb); halv_cross<1, 0>(v, lb);
    stage_J4(v, one, m1); stage_J2(v, one, m1); stage_J1(v, one, m1);
    rev_cross<31, 4>(v, lb);                                         // m=256
    halv_cross<8, 3>(v, lb); halv_cross<4, 2>(v, lb);
    halv_cross<2, 1>(v, lb); halv_cross<1, 0>(v, lb);
    stage_J4(v, one, m1); stage_J2(v, one, m1); stage_J1(v, one, m1);
    // sorted: slot i = 8*lane + r ascending; slots 193..255 = 1e30

    // ---- 4. back to float, boundary, sigma, sdt prefix -----------------------
    float f[VR];
#pragma unroll
    for (int e = 0; e < VR; e++) f[e] = __uint_as_float(v[e]);

    const float tnext = __uint_as_float(__shfl_down_sync(FULL, v[0], 1));
    const bool active = (lane < 24);

    float pfx[VR];
    {
        float4 s0 = make_float4(0.f,0.f,0.f,0.f), s1 = s0;
        if (active) {
            const float4* sp = reinterpret_cast<const float4*>(srow + lane * VR);
            s0 = __ldg(sp); s1 = __ldg(sp + 1);
        }
        const float sarr[VR] = {s0.x,s0.y,s0.z,s0.w,s1.x,s1.y,s1.z,s1.w};
        float run = 0.f;
#pragma unroll
        for (int e = 0; e < VR; e++) {
            float tn = (e < VR - 1) ? f[e + 1] : tnext;
            run += sarr[e] * (tn - f[e]);   // pad lanes: 0 * finite = 0
            pfx[e] = run;
        }
    }

    // ---- 5. warp exclusive scan ------------------------------------------------
    const float tot = pfx[VR - 1];
    float inc = tot;
#pragma unroll
    for (int d = 1; d < 32; d <<= 1) {
        float y = __shfl_up_sync(FULL, inc, d);
        if (lane >= d) inc += y;
    }
    const float excl = inc - tot;

    // ---- 6. weights ---------------------------------------------------------------
    float w[VR];
    {
        float prevE = __expf(-excl);
#pragma unroll
        for (int e = 0; e < VR; e++) {
            float E = __expf(-(excl + pfx[e]));
            w[e] = prevE - E;
            prevE = E;
        }
    }

    // ---- 7. wi out: direct STG.128 (blocked) ----------------------------------------
    if (active) {
        float4* wp = reinterpret_cast<float4*>(out_wi + (size_t)ray * NS + lane * VR);
        wp[0] = make_float4(w[0], w[1], w[2], w[3]);
        wp[1] = make_float4(w[4], w[5], w[6], w[7]);
    }

    // ---- 8. rgb from shared c, compile-time channels ----------------------------------
    cp_async_wait_all();
    __syncwarp();

    float a0 = 0.f, a1 = 0.f, a2 = 0.f;
    if (active) {
        const float* cl = reinterpret_cast<const float*>(shw) + lane * 24;
#pragma unroll
        for (int q = 0; q < 6; q++) {
            float4 cv = *reinterpret_cast<const float4*>(cl + 4 * q);
            const float cj[4] = {cv.x, cv.y, cv.z, cv.w};
#pragma unroll
            for (int j = 0; j < 4; j++) {
                const int k  = 4 * q + j;
                const int e  = k / 3;
                const int ch = k - 3 * e;
                const float p = w[e] * cj[j];
                if (ch == 0)      a0 += p;
                else if (ch == 1) a1 += p;
                else              a2 += p;
            }
        }
    }

    // ---- 9. reduce rgb, write ---------------------------------------------------------
#pragma unroll
    for (int d = 16; d > 0; d >>= 1) {
        a0 += __shfl_xor_sync(FULL, a0, d);
        a1 += __shfl_xor_sync(FULL, a1, d);
        a2 += __shfl_xor_sync(FULL, a2, d);
    }
    if (lane < 3) {
        const float val = (lane == 0) ? a0 : ((lane == 1) ? a1 : a2);
        out_rgb[(size_t)ray * 3 + lane] = val;
    }
}

extern "C" void kernel_launch(void* const* d_in, const int* in_sizes, int n_in,
                              void* d_out, int out_size) {
    const float* t     = (const float*)d_in[0];
    const float* sigma = (const float*)d_in[1];
    const float* c     = (const float*)d_in[2];

    const int R = in_sizes[0] / NP1;

    float* out_rgb = (float*)d_out;
    float* out_wi  = out_rgb + (size_t)R * 3;

    const int blocks = (R + WPB - 1) / WPB;
    nerf_integrate_kernel<<<blocks, WPB * 32>>>(t, sigma, c, out_rgb, out_wi, R);
}

// round 15
// speedup vs baseline: 1.1370x; 1.0021x over previous
#include <cuda_runtime.h>
#include <cstdint>

// NerfRender integrate v12: v11 + 2-IMNMX comparators (IMAD recovery removed —
// ncu shows IMAD lands on the ALU pipe, so the 3-op form was strictly worse),
// pruned Batcher front (16 comparators). One warp per ray.
// R = 65536, N = 192 (t has 193). Output: rgb [R,3] then wi [R,192].

#define NP1 193
#define NS  192
#define VR  8
#define WPB 8
#define SH_PER_WARP 576       // c only (144 chunks of 16B)
#define FULL 0xffffffffu
#define PAD_BITS 0x7149f2cau  // 1e30f: sorts above all real t, finite math

typedef uint32_t u32;

__device__ __forceinline__ void cp_async16(u32 saddr, const void* gptr) {
    asm volatile("cp.async.cg.shared.global [%0], [%1], 16;\n" :: "r"(saddr), "l"(gptr));
}
__device__ __forceinline__ void cp_async_commit() {
    asm volatile("cp.async.commit_group;\n" ::: "memory");
}
__device__ __forceinline__ void cp_async_wait_all() {
    asm volatile("cp.async.wait_group 0;\n" ::: "memory");
}

// ---- lane bits ---------------------------------------------------------------
struct LB { bool b0, b1, b2, b3, b4; };
template <int I>
__device__ __forceinline__ bool getb(const LB& lb) {
    if constexpr (I == 0)      return lb.b0;
    else if constexpr (I == 1) return lb.b1;
    else if constexpr (I == 2) return lb.b2;
    else if constexpr (I == 3) return lb.b3;
    else                       return lb.b4;
}

// ---- comparator: 2x IMNMX.U32, min to a --------------------------------------
__device__ __forceinline__ void ce(u32& a, u32& b) {
    const u32 mn = min(a, b);
    b = max(a, b);
    a = mn;
}

// Batcher odd-even sort-8, pruned: v[7] is PAD(max) in every lane, so
// comparators (3,7),(5,7),(6,7) are universal no-ops. 16 comparators.
#define CE(x, y) ce(v[x], v[y])
__device__ __forceinline__ void batcher8(u32 (&v)[VR]) {
    CE(0,1); CE(2,3); CE(4,5);
    CE(0,2); CE(1,3); CE(4,6);
    CE(1,2); CE(5,6);
    CE(0,4); CE(1,5); CE(2,6);
    CE(2,4); CE(3,5);
    CE(1,2); CE(3,4); CE(5,6);
}
__device__ __forceinline__ void stage_J1(u32 (&v)[VR]) {
    CE(0,1); CE(2,3); CE(4,5); CE(6,7);
}
__device__ __forceinline__ void stage_J2(u32 (&v)[VR]) {
    CE(0,2); CE(1,3); CE(4,6); CE(5,7);
}
__device__ __forceinline__ void stage_J4(u32 (&v)[VR]) {
    CE(0,4); CE(1,5); CE(2,6); CE(3,7);
}
#undef CE

// cross-lane reversal: partner lane^LMASK, partner reg 7-r; keepMin = !laneBit(KB)
template <int LMASK, int KB>
__device__ __forceinline__ void rev_cross(u32 (&v)[VR], const LB& lb) {
    u32 o[VR];
#pragma unroll
    for (int r = 0; r < VR; r++) o[r] = __shfl_xor_sync(FULL, v[7 - r], LMASK);
    const bool keep = !getb<KB>(lb);
#pragma unroll
    for (int r = 0; r < VR; r++)
        v[r] = keep ? min(v[r], o[r]) : max(v[r], o[r]);   // 1 IMNMX(P)
}
// cross-lane halving: partner lane^LJ, same reg
template <int LJ, int KB>
__device__ __forceinline__ void halv_cross(u32 (&v)[VR], const LB& lb) {
    u32 o[VR];
#pragma unroll
    for (int r = 0; r < VR; r++) o[r] = __shfl_xor_sync(FULL, v[r], LJ);
    const bool keep = !getb<KB>(lb);
#pragma unroll
    for (int r = 0; r < VR; r++)
        v[r] = keep ? min(v[r], o[r]) : max(v[r], o[r]);
}

__global__ __launch_bounds__(WPB * 32)
void nerf_integrate_kernel(const float* __restrict__ t,
                           const float* __restrict__ sigma,
                           const float* __restrict__ c,
                           float* __restrict__ out_rgb,
                           float* __restrict__ out_wi,
                           int R) {
    const int warp = threadIdx.x >> 5;
    const int lane = threadIdx.x & 31;
    const int ray  = blockIdx.x * WPB + warp;
    if (ray >= R) return;

    __shared__ u32 sh[WPB][SH_PER_WARP];    // c region only
    u32* shw = sh[warp];

    const LB lb = { (lane & 1) != 0, (lane & 2) != 0, (lane & 4) != 0,
                    (lane & 8) != 0, (lane & 16) != 0 };

    const u32*   trow = reinterpret_cast<const u32*>(t) + (size_t)ray * NP1;
    const float* srow = sigma + (size_t)ray * NS;
    const float* crow = c + (size_t)ray * NS * 3;

    // ---- 1. t loads straight into sort slots (placement-agnostic network) --
    u32 v[VR];
#pragma unroll
    for (int r = 0; r < 6; r++) v[r] = __ldg(trow + r * 32 + lane);
    v[6] = (lane == 0) ? __ldg(trow + 192) : PAD_BITS;
    v[7] = PAD_BITS;

    // ---- 2. prefetch c via cp.async (contiguous) ----------------------------
    {
        const u32 shc = (u32)__cvta_generic_to_shared(shw);
        const float4* c4 = reinterpret_cast<const float4*>(crow);
#pragma unroll
        for (int e = 0; e < 4; e++)
            cp_async16(shc + (e * 32 + lane) * 16, c4 + e * 32 + lane);
        if (lane < 16)
            cp_async16(shc + (128 + lane) * 16, c4 + 128 + lane);
        cp_async_commit();
    }

    // ---- 3. sort: pruned Batcher-8 per lane, reversal-form bitonic merges ----
    batcher8(v);                                                     // 8-sorted
    rev_cross<1, 0>(v, lb);                                          // m=16
    stage_J4(v); stage_J2(v); stage_J1(v);
    rev_cross<3, 1>(v, lb);                                          // m=32
    halv_cross<1, 0>(v, lb);
    stage_J4(v); stage_J2(v); stage_J1(v);
    rev_cross<7, 2>(v, lb);                                          // m=64
    halv_cross<2, 1>(v, lb); halv_cross<1, 0>(v, lb);
    stage_J4(v); stage_J2(v); stage_J1(v);
    rev_cross<15, 3>(v, lb);                                         // m=128
    halv_cross<4, 2>(v, lb); halv_cross<2, 1>(v, lb); halv_cross<1, 0>(v, lb);
    stage_J4(v); stage_J2(v); stage_J1(v);
    rev_cross<31, 4>(v, lb);                                         // m=256
    halv_cross<8, 3>(v, lb); halv_cross<4, 2>(v, lb);
    halv_cross<2, 1>(v, lb); halv_cross<1, 0>(v, lb);
    stage_J4(v); stage_J2(v); stage_J1(v);
    // sorted: slot i = 8*lane + r ascending; slots 193..255 = 1e30

    // ---- 4. back to float, boundary, sigma, sdt prefix -----------------------
    float f[VR];
#pragma unroll
    for (int e = 0; e < VR; e++) f[e] = __uint_as_float(v[e]);

    const float tnext = __uint_as_float(__shfl_down_sync(FULL, v[0], 1));
    const bool active = (lane < 24);

    float pfx[VR];
    {
        float4 s0 = make_float4(0.f,0.f,0.f,0.f), s1 = s0;
        if (active) {
            const float4* sp = reinterpret_cast<const float4*>(srow + lane * VR);
            s0 = __ldg(sp); s1 = __ldg(sp + 1);
        }
        const float sarr[VR] = {s0.x,s0.y,s0.z,s0.w,s1.x,s1.y,s1.z,s1.w};
        float run = 0.f;
#pragma unroll
        for (int e = 0; e < VR; e++) {
            float tn = (e < VR - 1) ? f[e + 1] : tnext;
            run += sarr[e] * (tn - f[e]);   // pad lanes: 0 * finite = 0
            pfx[e] = run;
        }
    }

    // ---- 5. warp exclusive scan ------------------------------------------------
    const float tot = pfx[VR - 1];
    float inc = tot;
#pragma unroll
    for (int d = 1; d < 32; d <<= 1) {
        float y = __shfl_up_sync(FULL, inc, d);
        if (lane >= d) inc += y;
    }
    const float excl = inc - tot;

    // ---- 6. weights ---------------------------------------------------------------
    float w[VR];
    {
        float prevE = __expf(-excl);
#pragma unroll
        for (int e = 0; e < VR; e++) {
            float E = __expf(-(excl + pfx[e]));
            w[e] = prevE - E;
            prevE = E;
        }
    }

    // ---- 7. wi out: direct STG.128 (blocked) ----------------------------------------
    if (active) {
        float4* wp = reinterpret_cast<float4*>(out_wi + (size_t)ray * NS + lane * VR);
        wp[0] = make_float4(w[0], w[1], w[2], w[3]);
        wp[1] = make_float4(w[4], w[5], w[6], w[7]);
    }

    // ---- 8. rgb from shared c, compile-time channels ----------------------------------
    cp_async_wait_all();
    __syncwarp();

    float a0 = 0.f, a1 = 0.f, a2 = 0.f;
    if (active) {
        const float* cl = reinterpret_cast<const float*>(shw) + lane * 24;
#pragma unroll
        for (int q = 0; q < 6; q++) {
            float4 cv = *reinterpret_cast<const float4*>(cl + 4 * q);
            const float cj[4] = {cv.x, cv.y, cv.z, cv.w};
#pragma unroll
            for (int j = 0; j < 4; j++) {
                const int k  = 4 * q + j;
                const int e  = k / 3;
                const int ch = k - 3 * e;
                const float p = w[e] * cj[j];
                if (ch == 0)      a0 += p;
                else if (ch == 1) a1 += p;
                else              a2 += p;
            }
        }
    }

    // ---- 9. reduce rgb, write ---------------------------------------------------------
#pragma unroll
    for (int d = 16; d > 0; d >>= 1) {
        a0 += __shfl_xor_sync(FULL, a0, d);
        a1 += __shfl_xor_sync(FULL, a1, d);
        a2 += __shfl_xor_sync(FULL, a2, d);
    }
    if (lane < 3) {
        const float val = (lane == 0) ? a0 : ((lane == 1) ? a1 : a2);
        out_rgb[(size_t)ray * 3 + lane] = val;
    }
}

extern "C" void kernel_launch(void* const* d_in, const int* in_sizes, int n_in,
                              void* d_out, int out_size) {
    const float* t     = (const float*)d_in[0];
    const float* sigma = (const float*)d_in[1];
    const float* c     = (const float*)d_in[2];

    const int R = in_sizes[0] / NP1;

    float* out_rgb = (float*)d_out;
    float* out_wi  = out_rgb + (size_t)R * 3;

    const int blocks = (R + WPB - 1) / WPB;
    nerf_integrate_kernel<<<blocks, WPB * 32>>>(t, sigma, c, out_rgb, out_wi, R);
}